// round 3
// baseline (speedup 1.0000x reference)
#include <cuda_runtime.h>
#include <math.h>

#define TT   256
#define BB   128
#define DD   1024
#define HH   1024
#define DH   2048
#define N4H  4096
#define BH   (BB*HH)

typedef unsigned long long ull;

// Scratch (device globals — no allocation allowed)
__device__ float g_pre[(size_t)TT * BB * N4H];  // x-projection + bias, [T*B, 4H] (gate-major: f,i,g,o)
__device__ float g_c[BH];                        // cell state [b, j]
__device__ float g_hT[HH * BB];                  // transposed hidden state [j, b]

// ---- packed fp32x2 helpers (sm_103a dual fp32 pipe; ptxas never auto-fuses) ----
__device__ __forceinline__ ull pack2(float lo, float hi) {
    ull r; asm("mov.b64 %0, {%1, %2};" : "=l"(r) : "f"(lo), "f"(hi)); return r;
}
__device__ __forceinline__ void unpack2(ull v, float& lo, float& hi) {
    asm("mov.b64 {%0, %1}, %2;" : "=f"(lo), "=f"(hi) : "l"(v));
}
__device__ __forceinline__ ull fma2(ull a, ull b, ull c) {
    ull d; asm("fma.rn.f32x2 %0, %1, %2, %3;" : "=l"(d) : "l"(a), "l"(b), "l"(c)); return d;
}
__device__ __forceinline__ float sigmoidf_(float x) { return 1.0f / (1.0f + expf(-x)); }

// ============================================================================
// Pre-GEMM: g_pre[T*B, 4H] = X[T*B, D] @ Wx^T + bias   (unchanged, ~fp32 peak)
// ============================================================================
__global__ __launch_bounds__(256, 2) void pre_gemm_kernel(
    const float* __restrict__ X,
    const float* __restrict__ Wf, const float* __restrict__ Wi,
    const float* __restrict__ Wg, const float* __restrict__ Wo,
    const float* __restrict__ bf, const float* __restrict__ bi,
    const float* __restrict__ bg, const float* __restrict__ bo)
{
    __shared__ float As[8][128];
    __shared__ float Bs[8][128];

    const int tid = threadIdx.x;
    const int bm  = blockIdx.y * 128;
    const int bn  = blockIdx.x * 128;
    const int gate = bn >> 10;

    const float* Wt = (gate == 0) ? Wf : (gate == 1) ? Wi : (gate == 2) ? Wg : Wo;
    const float* bt = (gate == 0) ? bf : (gate == 1) ? bi : (gate == 2) ? bg : bo;

    const int arow = tid >> 1;
    const int ka   = (tid & 1) * 4;
    const int ncol = tid >> 1;
    const int kb   = (tid & 1) * 4;
    const float* wrow = Wt + (size_t)((bn & 1023) + ncol) * DH;
    const float* xrow = X  + (size_t)(bm + arow) * DD;

    const int tx = tid & 15, ty = tid >> 4;

    ull accp[8][4];
#pragma unroll
    for (int i = 0; i < 8; i++)
#pragma unroll
        for (int jp = 0; jp < 4; jp++) accp[i][jp] = 0ULL;

    float4 va = *(const float4*)(xrow + ka);
    float4 vb = *(const float4*)(wrow + kb);

    for (int k0 = 0; k0 < DD; k0 += 8) {
        As[ka+0][arow] = va.x; As[ka+1][arow] = va.y; As[ka+2][arow] = va.z; As[ka+3][arow] = va.w;
        Bs[kb+0][ncol] = vb.x; Bs[kb+1][ncol] = vb.y; Bs[kb+2][ncol] = vb.z; Bs[kb+3][ncol] = vb.w;
        __syncthreads();
        if (k0 + 8 < DD) {
            va = *(const float4*)(xrow + k0 + 8 + ka);
            vb = *(const float4*)(wrow + k0 + 8 + kb);
        }
#pragma unroll
        for (int kk = 0; kk < 8; kk++) {
            float4 a0 = *(const float4*)&As[kk][ty*8];
            float4 a1 = *(const float4*)&As[kk][ty*8 + 4];
            ull b[4];
#pragma unroll
            for (int jp = 0; jp < 4; jp++)
                b[jp] = *(const ull*)&Bs[kk][tx*8 + jp*2];
            float as[8] = {a0.x, a0.y, a0.z, a0.w, a1.x, a1.y, a1.z, a1.w};
#pragma unroll
            for (int i = 0; i < 8; i++) {
                ull a2 = pack2(as[i], as[i]);
#pragma unroll
                for (int jp = 0; jp < 4; jp++)
                    accp[i][jp] = fma2(a2, b[jp], accp[i][jp]);
            }
        }
        __syncthreads();
    }

    float biasv[8];
#pragma unroll
    for (int j = 0; j < 8; j++)
        biasv[j] = bt[(bn & 1023) + tx*8 + j];

#pragma unroll
    for (int i = 0; i < 8; i++) {
        size_t r = (size_t)(bm + ty*8 + i);
        float o[8];
#pragma unroll
        for (int jp = 0; jp < 4; jp++) unpack2(accp[i][jp], o[jp*2], o[jp*2+1]);
#pragma unroll
        for (int j = 0; j < 8; j++) o[j] += biasv[j];
        float4* dst = (float4*)&g_pre[r * N4H + bn + tx*8];
        dst[0] = make_float4(o[0], o[1], o[2], o[3]);
        dst[1] = make_float4(o[4], o[5], o[6], o[7]);
    }
}

// ============================================================================
// Per-step kernel v2: 512 threads, split-K across two 256-thread halves
// (half h does K in [h*512, h*512+512)), double-buffered smem tiles, one
// __syncthreads per tile. Halves combine gates in smem, then fused cell update.
// ============================================================================
#define STEP_SMEM_BYTES ((2*2*16*128 + 2*2*16*34 + 128*33) * 4)

__global__ __launch_bounds__(512) void lstm_step_kernel(
    const float* __restrict__ Wf, const float* __restrict__ Wi,
    const float* __restrict__ Wg, const float* __restrict__ Wo,
    int t, float* __restrict__ out)
{
    extern __shared__ float sm[];
    float* Hs  = sm;              // [half][buf][kk][128]  8192 floats
    float* Wsm = sm + 8192;       // [half][buf][kk][34]   2176 floats
    float* Gs  = Wsm + 2176;      // [128][33]             4224 floats

#define HS(h,b,k,x)  Hs[((((h)*2+(b))*16+(k))<<7) + (x)]
#define WSX(h,b,k,x) Wsm[((((h)*2+(b))*16+(k))*34) + (x)]
#define GSX(r,c)     Gs[(r)*33 + (c)]

    const int tid  = threadIdx.x;
    const int half = tid >> 8;       // 0 or 1 : K-half
    const int lt   = tid & 255;
    const int j0   = blockIdx.x * 8;
    const int rg   = lt >> 3;        // 0..31 -> 4 rows each
    const int cg   = lt & 7;         // 0..7  -> 4 cols each
    const int kbase = half << 9;     // 0 or 512

    // Prefetch pre-activation tile (half 0 threads own it; hides DRAM under GEMM)
    float pre_r[4][4];
    if (half == 0) {
        const float* preb = g_pre + (size_t)t * BB * N4H;
#pragma unroll
        for (int i = 0; i < 4; i++) {
            int row = rg*4 + i;
#pragma unroll
            for (int j = 0; j < 4; j++) {
                int col = cg*4 + j;
                int gate = col >> 3, jl = col & 7;
                pre_r[i][j] = preb[(size_t)row * N4H + gate*1024 + j0 + jl];
            }
        }
    }

    ull accp[4][2] = {{0ULL,0ULL},{0ULL,0ULL},{0ULL,0ULL},{0ULL,0ULL}};

    if (t > 0) {
        const int hk   = lt >> 4;          // 0..15 (k within tile)
        const int hseg = (lt & 15) * 8;    // b segment
        const int wn   = lt >> 2;          // 0..31 (cols), valid lt<128
        const int wkk  = (lt & 3) * 4;
        const float* wrow = Wf;
        if (lt < 128) {
            int gate = wn >> 3, jl = wn & 7;
            const float* Wt = (gate == 0) ? Wf : (gate == 1) ? Wi : (gate == 2) ? Wg : Wo;
            wrow = Wt + (size_t)(j0 + jl) * DH + DD + kbase;   // recurrent cols, this K-half
        }

        float4 h0 = *(const float4*)&g_hT[(size_t)(kbase + hk) * BB + hseg];
        float4 h1 = *(const float4*)&g_hT[(size_t)(kbase + hk) * BB + hseg + 4];
        float4 wv = make_float4(0.f, 0.f, 0.f, 0.f);
        if (lt < 128) wv = *(const float4*)(wrow + wkk);

        // prime buffer 0
        *(float4*)&HS(half,0,hk,hseg)   = h0;
        *(float4*)&HS(half,0,hk,hseg+4) = h1;
        if (lt < 128) {
            WSX(half,0,wkk+0,wn) = wv.x; WSX(half,0,wkk+1,wn) = wv.y;
            WSX(half,0,wkk+2,wn) = wv.z; WSX(half,0,wkk+3,wn) = wv.w;
        }
        __syncthreads();

        int buf = 0;
        for (int k0 = 0; k0 < 512; k0 += 16) {
            // prefetch next tile from global while computing this one
            if (k0 + 16 < 512) {
                h0 = *(const float4*)&g_hT[(size_t)(kbase + k0 + 16 + hk) * BB + hseg];
                h1 = *(const float4*)&g_hT[(size_t)(kbase + k0 + 16 + hk) * BB + hseg + 4];
                if (lt < 128) wv = *(const float4*)(wrow + k0 + 16 + wkk);
            }
#pragma unroll
            for (int kk = 0; kk < 16; kk++) {
                float4 av = *(const float4*)&HS(half,buf,kk,rg*4);
                ull b0 = *(const ull*)&WSX(half,buf,kk,cg*4);
                ull b1 = *(const ull*)&WSX(half,buf,kk,cg*4 + 2);
                float as[4] = {av.x, av.y, av.z, av.w};
#pragma unroll
                for (int i = 0; i < 4; i++) {
                    ull a2 = pack2(as[i], as[i]);
                    accp[i][0] = fma2(a2, b0, accp[i][0]);
                    accp[i][1] = fma2(a2, b1, accp[i][1]);
                }
            }
            if (k0 + 16 < 512) {
                *(float4*)&HS(half,buf^1,hk,hseg)   = h0;
                *(float4*)&HS(half,buf^1,hk,hseg+4) = h1;
                if (lt < 128) {
                    WSX(half,buf^1,wkk+0,wn) = wv.x; WSX(half,buf^1,wkk+1,wn) = wv.y;
                    WSX(half,buf^1,wkk+2,wn) = wv.z; WSX(half,buf^1,wkk+3,wn) = wv.w;
                }
            }
            __syncthreads();
            buf ^= 1;
        }
    }

    // combine halves: half0 stores (pre + its partial), half1 accumulates
    if (half == 0) {
#pragma unroll
        for (int i = 0; i < 4; i++) {
            int row = rg*4 + i;
            float o[4];
            unpack2(accp[i][0], o[0], o[1]);
            unpack2(accp[i][1], o[2], o[3]);
#pragma unroll
            for (int j = 0; j < 4; j++)
                GSX(row, cg*4 + j) = o[j] + pre_r[i][j];
        }
    }
    __syncthreads();
    if (half == 1) {
#pragma unroll
        for (int i = 0; i < 4; i++) {
            int row = rg*4 + i;
            float o[4];
            unpack2(accp[i][0], o[0], o[1]);
            unpack2(accp[i][1], o[2], o[3]);
#pragma unroll
            for (int j = 0; j < 4; j++)
                GSX(row, cg*4 + j) += o[j];
        }
    }
    __syncthreads();

    // fused cell update: 1024 (b,j) pairs, 2 per thread
#pragma unroll
    for (int pp = 0; pp < 2; pp++) {
        int p  = tid + pp * 512;
        int b  = p >> 3;
        int jl = p & 7;
        float fg = sigmoidf_(GSX(b, jl));
        float ig = sigmoidf_(GSX(b, 8  + jl));
        float gg = tanhf   (GSX(b, 16 + jl));
        float og = sigmoidf_(GSX(b, 24 + jl));
        int cidx = b * HH + j0 + jl;
        float cold = (t > 0) ? g_c[cidx] : 0.0f;
        float cnew = fg * cold + ig * gg;
        float h    = og * tanhf(cnew);
        g_c[cidx] = cnew;
        g_hT[(size_t)(j0 + jl) * BB + b] = h;          // transposed for next step
        out[(size_t)t * BH + cidx]       = h;          // outputs[t]
    }
#undef HS
#undef WSX
#undef GSX
}

__global__ void finalize_kernel(float* __restrict__ out, int write_state) {
    int i = blockIdx.x * blockDim.x + threadIdx.x;
    if (i < BH && write_state) {
        out[(size_t)TT * BH + i]       = out[(size_t)(TT - 1) * BH + i];  // hx
        out[(size_t)TT * BH + BH + i]  = g_c[i];                           // cx
    }
}

extern "C" void kernel_launch(void* const* d_in, const int* in_sizes, int n_in,
                              void* d_out, int out_size) {
    const float* X  = (const float*)d_in[0];
    const float* Wf = (const float*)d_in[1];
    const float* bf = (const float*)d_in[2];
    const float* Wi = (const float*)d_in[3];
    const float* bi = (const float*)d_in[4];
    const float* Wg = (const float*)d_in[5];
    const float* bg = (const float*)d_in[6];
    const float* Wo = (const float*)d_in[7];
    const float* bo = (const float*)d_in[8];
    float* out = (float*)d_out;

    // dynamic smem opt-in (58368 B > 48KB static limit); immediate, capture-safe
    cudaFuncSetAttribute(lstm_step_kernel,
                         cudaFuncAttributeMaxDynamicSharedMemorySize, STEP_SMEM_BYTES);

    // 1) time-parallel input projection (+bias) for all gates
    dim3 pgrid(N4H / 128, (TT * BB) / 128);
    pre_gemm_kernel<<<pgrid, 256>>>(X, Wf, Wi, Wg, Wo, bf, bi, bg, bo);

    // 2) sequential recurrence, one fused kernel per step
    for (int t = 0; t < TT; t++)
        lstm_step_kernel<<<HH / 8, 512, STEP_SMEM_BYTES>>>(Wf, Wi, Wg, Wo, t, out);

    // 3) final hx / cx
    int ws = (out_size >= TT * BH + 2 * BH) ? 1 : 0;
    finalize_kernel<<<(BH + 255) / 256, 256>>>(out, ws);
}

// round 4
// speedup vs baseline: 1.2340x; 1.2340x over previous
#include <cuda_runtime.h>
#include <math.h>

#define TT   256
#define BB   128
#define DD   1024
#define HH   1024
#define DH   2048
#define N4H  4096
#define BH   (BB*HH)

typedef unsigned long long ull;

// Scratch (device globals — no allocation allowed)
__device__ float g_pre[(size_t)TT * BB * N4H];  // x-projection + bias, [T*B, 4H] gate-major
__device__ float g_c[BH];                        // cell state [b, j]
__device__ float g_hT[HH * BB];                  // transposed hidden state [j, b]

// ---- packed fp32x2 helpers ----
__device__ __forceinline__ ull pack2(float lo, float hi) {
    ull r; asm("mov.b64 %0, {%1, %2};" : "=l"(r) : "f"(lo), "f"(hi)); return r;
}
__device__ __forceinline__ void unpack2(ull v, float& lo, float& hi) {
    asm("mov.b64 {%0, %1}, %2;" : "=f"(lo), "=f"(hi) : "l"(v));
}
__device__ __forceinline__ ull fma2(ull a, ull b, ull c) {
    ull d; asm("fma.rn.f32x2 %0, %1, %2, %3;" : "=l"(d) : "l"(a), "l"(b), "l"(c)); return d;
}
__device__ __forceinline__ float sigmoidf_(float x) { return 1.0f / (1.0f + expf(-x)); }

// ============================================================================
// Pre-GEMM: g_pre[T*B, 4H] = X[T*B, D] @ Wx^T + bias   (unchanged)
// ============================================================================
__global__ __launch_bounds__(256, 2) void pre_gemm_kernel(
    const float* __restrict__ X,
    const float* __restrict__ Wf, const float* __restrict__ Wi,
    const float* __restrict__ Wg, const float* __restrict__ Wo,
    const float* __restrict__ bf, const float* __restrict__ bi,
    const float* __restrict__ bg, const float* __restrict__ bo)
{
    __shared__ float As[8][128];
    __shared__ float Bs[8][128];

    const int tid = threadIdx.x;
    const int bm  = blockIdx.y * 128;
    const int bn  = blockIdx.x * 128;
    const int gate = bn >> 10;

    const float* Wt = (gate == 0) ? Wf : (gate == 1) ? Wi : (gate == 2) ? Wg : Wo;
    const float* bt = (gate == 0) ? bf : (gate == 1) ? bi : (gate == 2) ? bg : bo;

    const int arow = tid >> 1;
    const int ka   = (tid & 1) * 4;
    const int ncol = tid >> 1;
    const int kb   = (tid & 1) * 4;
    const float* wrow = Wt + (size_t)((bn & 1023) + ncol) * DH;
    const float* xrow = X  + (size_t)(bm + arow) * DD;

    const int tx = tid & 15, ty = tid >> 4;

    ull accp[8][4];
#pragma unroll
    for (int i = 0; i < 8; i++)
#pragma unroll
        for (int jp = 0; jp < 4; jp++) accp[i][jp] = 0ULL;

    float4 va = *(const float4*)(xrow + ka);
    float4 vb = *(const float4*)(wrow + kb);

    for (int k0 = 0; k0 < DD; k0 += 8) {
        As[ka+0][arow] = va.x; As[ka+1][arow] = va.y; As[ka+2][arow] = va.z; As[ka+3][arow] = va.w;
        Bs[kb+0][ncol] = vb.x; Bs[kb+1][ncol] = vb.y; Bs[kb+2][ncol] = vb.z; Bs[kb+3][ncol] = vb.w;
        __syncthreads();
        if (k0 + 8 < DD) {
            va = *(const float4*)(xrow + k0 + 8 + ka);
            vb = *(const float4*)(wrow + k0 + 8 + kb);
        }
#pragma unroll
        for (int kk = 0; kk < 8; kk++) {
            float4 a0 = *(const float4*)&As[kk][ty*8];
            float4 a1 = *(const float4*)&As[kk][ty*8 + 4];
            ull b[4];
#pragma unroll
            for (int jp = 0; jp < 4; jp++)
                b[jp] = *(const ull*)&Bs[kk][tx*8 + jp*2];
            float as[8] = {a0.x, a0.y, a0.z, a0.w, a1.x, a1.y, a1.z, a1.w};
#pragma unroll
            for (int i = 0; i < 8; i++) {
                ull a2 = pack2(as[i], as[i]);
#pragma unroll
                for (int jp = 0; jp < 4; jp++)
                    accp[i][jp] = fma2(a2, b[jp], accp[i][jp]);
            }
        }
        __syncthreads();
    }

    float biasv[8];
#pragma unroll
    for (int j = 0; j < 8; j++)
        biasv[j] = bt[(bn & 1023) + tx*8 + j];

#pragma unroll
    for (int i = 0; i < 8; i++) {
        size_t r = (size_t)(bm + ty*8 + i);
        float o[8];
#pragma unroll
        for (int jp = 0; jp < 4; jp++) unpack2(accp[i][jp], o[jp*2], o[jp*2+1]);
#pragma unroll
        for (int j = 0; j < 8; j++) o[j] += biasv[j];
        float4* dst = (float4*)&g_pre[r * N4H + bn + tx*8];
        dst[0] = make_float4(o[0], o[1], o[2], o[3]);
        dst[1] = make_float4(o[4], o[5], o[6], o[7]);
    }
}

// ============================================================================
// Step kernel v3: 256 threads = 4 K-splits x 64 threads. Each split computes
// the full 128x32 tile over K=256 with an 8x8 per-thread register tile
// (1 B/FMA smem traffic, 32 independent fma2 chains). Partials reduced via
// smem overlay, then fused cell update.
// ============================================================================
#define SPLITS 4
#define BK     8
#define KSP    (HH / SPLITS)          // 256
// Hs[s][buf][BK][128] = 8192 floats; Ws[s][buf][BK][36] = 2304 floats (10496 total)
// Gp[s][128][33] overlay = 16896 floats  ->  alloc max = 16896 floats
#define HS_OFF 0
#define WS_OFF 8192
#define STEP_SMEM_BYTES (16896 * 4)

#define HS(s,b,k,x)  sm[HS_OFF + ((((s)*2+(b))*BK+(k))<<7) + (x)]
#define WS(s,b,k,x)  sm[WS_OFF + ((((s)*2+(b))*BK+(k))*36) + (x)]
#define GP(s,r,c)    sm[(((s)*128+(r))*33) + (c)]

__global__ __launch_bounds__(256) void lstm_step_kernel(
    const float* __restrict__ Wf, const float* __restrict__ Wi,
    const float* __restrict__ Wg, const float* __restrict__ Wo,
    int t, float* __restrict__ out)
{
    extern __shared__ float sm[];

    const int tid   = threadIdx.x;
    const int split = tid >> 6;        // 0..3
    const int lt    = tid & 63;
    const int j0    = blockIdx.x * 8;
    const int ty    = lt >> 2;         // 0..15 -> rows ty*8..ty*8+7
    const int tx    = lt & 3;          // 0..3  -> cols tx*8..tx*8+7
    const int kbase = split * KSP;

    // ---- prefetch pre-activations + old cell state (hidden under GEMM) ----
    const float* preb = g_pre + (size_t)t * BB * N4H;
    float pr[4][4];
    float cold[4];
#pragma unroll
    for (int pp = 0; pp < 4; pp++) {
        int idx = tid + pp * 256;
        int b   = idx >> 3;
        int jl  = idx & 7;
#pragma unroll
        for (int g = 0; g < 4; g++)
            pr[pp][g] = preb[(size_t)b * N4H + g*1024 + j0 + jl];
        cold[pp] = (t > 0) ? g_c[b * HH + j0 + jl] : 0.0f;
    }

    ull acc[4][8];
#pragma unroll
    for (int i = 0; i < 4; i++)
#pragma unroll
        for (int j = 0; j < 8; j++) acc[i][j] = 0ULL;

    if (t > 0) {
        // H stage: 4 float4/thread. row = i*2 + (lt>>5), cols (lt&31)*4
        const int hi = lt >> 5;
        const int x4 = (lt & 31) * 4;
        // W stage: 1 float4/thread. col c = lt>>1, k-quad q = lt&1
        const int wc = lt >> 1;            // 0..31
        const int wq = lt & 1;             // 0..1
        const int wgate = wc >> 3, wjl = wc & 7;
        const float* Wt = (wgate == 0) ? Wf : (wgate == 1) ? Wi : (wgate == 2) ? Wg : Wo;
        const float* wrow = Wt + (size_t)(j0 + wjl) * DH + DD + kbase + wq * 4;

        float4 hv[4];
#pragma unroll
        for (int i = 0; i < 4; i++)
            hv[i] = *(const float4*)&g_hT[(size_t)(kbase + i*2 + hi) * BB + x4];
        float4 wv = *(const float4*)(wrow);

        // prime buffer 0
#pragma unroll
        for (int i = 0; i < 4; i++)
            *(float4*)&HS(split, 0, i*2 + hi, x4) = hv[i];
        WS(split, 0, wq*4+0, wc) = wv.x; WS(split, 0, wq*4+1, wc) = wv.y;
        WS(split, 0, wq*4+2, wc) = wv.z; WS(split, 0, wq*4+3, wc) = wv.w;
        __syncthreads();

        int buf = 0;
        for (int k0 = 0; k0 < KSP; k0 += BK) {
            if (k0 + BK < KSP) {
#pragma unroll
                for (int i = 0; i < 4; i++)
                    hv[i] = *(const float4*)&g_hT[(size_t)(kbase + k0 + BK + i*2 + hi) * BB + x4];
                wv = *(const float4*)(wrow + k0 + BK);
            }
#pragma unroll
            for (int kk = 0; kk < BK; kk++) {
                // A: 8 rows as 4 packed f32x2 directly from LDS.128 (no MOVs)
                ulonglong2 av0 = *(const ulonglong2*)&HS(split, buf, kk, ty*8);
                ulonglong2 av1 = *(const ulonglong2*)&HS(split, buf, kk, ty*8 + 4);
                float4 bv0 = *(const float4*)&WS(split, buf, kk, tx*8);
                float4 bv1 = *(const float4*)&WS(split, buf, kk, tx*8 + 4);
                ull a[4] = {av0.x, av0.y, av1.x, av1.y};
                float bs[8] = {bv0.x, bv0.y, bv0.z, bv0.w, bv1.x, bv1.y, bv1.z, bv1.w};
#pragma unroll
                for (int j = 0; j < 8; j++) {
                    ull b2 = pack2(bs[j], bs[j]);
#pragma unroll
                    for (int i = 0; i < 4; i++)
                        acc[i][j] = fma2(a[i], b2, acc[i][j]);
                }
            }
            if (k0 + BK < KSP) {
#pragma unroll
                for (int i = 0; i < 4; i++)
                    *(float4*)&HS(split, buf^1, i*2 + hi, x4) = hv[i];
                WS(split, buf^1, wq*4+0, wc) = wv.x; WS(split, buf^1, wq*4+1, wc) = wv.y;
                WS(split, buf^1, wq*4+2, wc) = wv.z; WS(split, buf^1, wq*4+3, wc) = wv.w;
            }
            __syncthreads();
            buf ^= 1;
        }
    }

    // ---- write partials into Gp overlay (tile smem is dead now) ----
#pragma unroll
    for (int i2 = 0; i2 < 4; i2++) {
#pragma unroll
        for (int j = 0; j < 8; j++) {
            float lo, hi2;
            unpack2(acc[i2][j], lo, hi2);
            int col = tx*8 + j;
            GP(split, ty*8 + i2*2,     col) = lo;
            GP(split, ty*8 + i2*2 + 1, col) = hi2;
        }
    }
    __syncthreads();

    // ---- reduce 4 partials + pre, fused cell update: 4 (b,jl) pairs/thread ----
#pragma unroll
    for (int pp = 0; pp < 4; pp++) {
        int idx = tid + pp * 256;
        int b   = idx >> 3;
        int jl  = idx & 7;
        float gf = GP(0,b,jl)    + GP(1,b,jl)    + GP(2,b,jl)    + GP(3,b,jl)    + pr[pp][0];
        float gi = GP(0,b,8+jl)  + GP(1,b,8+jl)  + GP(2,b,8+jl)  + GP(3,b,8+jl)  + pr[pp][1];
        float gg = GP(0,b,16+jl) + GP(1,b,16+jl) + GP(2,b,16+jl) + GP(3,b,16+jl) + pr[pp][2];
        float go = GP(0,b,24+jl) + GP(1,b,24+jl) + GP(2,b,24+jl) + GP(3,b,24+jl) + pr[pp][3];
        float fg = sigmoidf_(gf);
        float ig = sigmoidf_(gi);
        float gv = tanhf(gg);
        float og = sigmoidf_(go);
        int cidx   = b * HH + j0 + jl;
        float cnew = fg * cold[pp] + ig * gv;
        float h    = og * tanhf(cnew);
        g_c[cidx] = cnew;
        g_hT[(size_t)(j0 + jl) * BB + b] = h;    // transposed for next step
        out[(size_t)t * BH + cidx]       = h;    // outputs[t]
    }
}

__global__ void finalize_kernel(float* __restrict__ out, int write_state) {
    int i = blockIdx.x * blockDim.x + threadIdx.x;
    if (i < BH && write_state) {
        out[(size_t)TT * BH + i]       = out[(size_t)(TT - 1) * BH + i];  // hx
        out[(size_t)TT * BH + BH + i]  = g_c[i];                           // cx
    }
}

extern "C" void kernel_launch(void* const* d_in, const int* in_sizes, int n_in,
                              void* d_out, int out_size) {
    const float* X  = (const float*)d_in[0];
    const float* Wf = (const float*)d_in[1];
    const float* bf = (const float*)d_in[2];
    const float* Wi = (const float*)d_in[3];
    const float* bi = (const float*)d_in[4];
    const float* Wg = (const float*)d_in[5];
    const float* bg = (const float*)d_in[6];
    const float* Wo = (const float*)d_in[7];
    const float* bo = (const float*)d_in[8];
    float* out = (float*)d_out;

    cudaFuncSetAttribute(lstm_step_kernel,
                         cudaFuncAttributeMaxDynamicSharedMemorySize, STEP_SMEM_BYTES);

    // 1) time-parallel input projection (+bias) for all gates
    dim3 pgrid(N4H / 128, (TT * BB) / 128);
    pre_gemm_kernel<<<pgrid, 256>>>(X, Wf, Wi, Wg, Wo, bf, bi, bg, bo);

    // 2) sequential recurrence
    for (int t = 0; t < TT; t++)
        lstm_step_kernel<<<HH / 8, 256, STEP_SMEM_BYTES>>>(Wf, Wi, Wg, Wo, t, out);

    // 3) final hx / cx
    int ws = (out_size >= TT * BH + 2 * BH) ? 1 : 0;
    finalize_kernel<<<(BH + 255) / 256, 256>>>(out, ws);
}

// round 10
// speedup vs baseline: 1.3974x; 1.1324x over previous
#include <cuda_runtime.h>
#include <cuda_bf16.h>
#include <math.h>

#define TT   256
#define BB   128
#define DD   1024
#define HH   1024
#define DH   2048
#define N4H  4096
#define BH   (BB*HH)

typedef unsigned long long ull;
typedef unsigned int uint;

// Scratch (device globals — no allocation allowed)
__device__ float g_pre[(size_t)TT * BB * N4H];       // x-projection + bias, gate-major
__device__ float g_c[BH];                             // cell state [b, j]
__device__ __nv_bfloat16 g_hhi[BH];                   // h split-high [b][k]
__device__ __nv_bfloat16 g_hlo[BH];                   // h split-low  [b][k]
__device__ __nv_bfloat16 g_whi[(size_t)N4H * HH];     // Wh split-high, block-ordered [(jblk*4+gate)*8+jl][k]
__device__ __nv_bfloat16 g_wlo[(size_t)N4H * HH];     // Wh split-low

// ---- packed fp32x2 helpers (pre-GEMM) ----
__device__ __forceinline__ ull pack2(float lo, float hi) {
    ull r; asm("mov.b64 %0, {%1, %2};" : "=l"(r) : "f"(lo), "f"(hi)); return r;
}
__device__ __forceinline__ void unpack2(ull v, float& lo, float& hi) {
    asm("mov.b64 {%0, %1}, %2;" : "=f"(lo), "=f"(hi) : "l"(v));
}
__device__ __forceinline__ ull fma2(ull a, ull b, ull c) {
    ull d; asm("fma.rn.f32x2 %0, %1, %2, %3;" : "=l"(d) : "l"(a), "l"(b), "l"(c)); return d;
}
__device__ __forceinline__ float sigmoidf_(float x) { return 1.0f / (1.0f + expf(-x)); }

// ---- mma helpers ----
__device__ __forceinline__ uint sptr(const void* p) { return (uint)__cvta_generic_to_shared(p); }
__device__ __forceinline__ void ldsm_x4(uint* r, uint addr) {
    asm volatile("ldmatrix.sync.aligned.m8n8.x4.shared.b16 {%0,%1,%2,%3}, [%4];"
        : "=r"(r[0]), "=r"(r[1]), "=r"(r[2]), "=r"(r[3]) : "r"(addr));
}
__device__ __forceinline__ void mma16816(float* c, const uint* a, const uint* b) {
    asm volatile("mma.sync.aligned.m16n8k16.row.col.f32.bf16.bf16.f32 "
        "{%0,%1,%2,%3}, {%4,%5,%6,%7}, {%8,%9}, {%0,%1,%2,%3};"
        : "+f"(c[0]), "+f"(c[1]), "+f"(c[2]), "+f"(c[3])
        : "r"(a[0]), "r"(a[1]), "r"(a[2]), "r"(a[3]), "r"(b[0]), "r"(b[1]));
}

// ============================================================================
// Weight split prep: Wh (recurrent region) -> bf16 hi/lo, block-ordered rows.
// Row n (0..4095): jblk = n>>5, gate = (n>>3)&3, jl = n&7.
// ============================================================================
__global__ void split_w_kernel(
    const float* __restrict__ Wf, const float* __restrict__ Wi,
    const float* __restrict__ Wg, const float* __restrict__ Wo)
{
    int idx = blockIdx.x * 256 + threadIdx.x;      // 0 .. 4096*1024-1
    int k = idx & 1023;
    int n = idx >> 10;
    int jblk = n >> 5, rem = n & 31, gate = rem >> 3, jl = rem & 7;
    const float* Wt = (gate == 0) ? Wf : (gate == 1) ? Wi : (gate == 2) ? Wg : Wo;
    float w = Wt[(size_t)(jblk * 8 + jl) * DH + DD + k];
    __nv_bfloat16 hi = __float2bfloat16(w);
    g_whi[idx] = hi;
    g_wlo[idx] = __float2bfloat16(w - __bfloat162float(hi));
}

// ============================================================================
// Pre-GEMM (fp32x2): g_pre = X @ Wx^T + bias
// ============================================================================
__global__ __launch_bounds__(256, 2) void pre_gemm_kernel(
    const float* __restrict__ X,
    const float* __restrict__ Wf, const float* __restrict__ Wi,
    const float* __restrict__ Wg, const float* __restrict__ Wo,
    const float* __restrict__ bf, const float* __restrict__ bi,
    const float* __restrict__ bg, const float* __restrict__ bo)
{
    __shared__ float As[8][128];
    __shared__ float Bs[8][128];

    const int tid = threadIdx.x;
    const int bm  = blockIdx.y * 128;
    const int bn  = blockIdx.x * 128;
    const int gate = bn >> 10;

    const float* Wt = (gate == 0) ? Wf : (gate == 1) ? Wi : (gate == 2) ? Wg : Wo;
    const float* bt = (gate == 0) ? bf : (gate == 1) ? bi : (gate == 2) ? bg : bo;

    const int arow = tid >> 1;
    const int ka   = (tid & 1) * 4;
    const int ncol = tid >> 1;
    const int kb   = (tid & 1) * 4;
    const float* wrow = Wt + (size_t)((bn & 1023) + ncol) * DH;
    const float* xrow = X  + (size_t)(bm + arow) * DD;

    const int tx = tid & 15, ty = tid >> 4;

    ull accp[8][4];
#pragma unroll
    for (int i = 0; i < 8; i++)
#pragma unroll
        for (int jp = 0; jp < 4; jp++) accp[i][jp] = 0ULL;

    float4 va = *(const float4*)(xrow + ka);
    float4 vb = *(const float4*)(wrow + kb);

    for (int k0 = 0; k0 < DD; k0 += 8) {
        As[ka+0][arow] = va.x; As[ka+1][arow] = va.y; As[ka+2][arow] = va.z; As[ka+3][arow] = va.w;
        Bs[kb+0][ncol] = vb.x; Bs[kb+1][ncol] = vb.y; Bs[kb+2][ncol] = vb.z; Bs[kb+3][ncol] = vb.w;
        __syncthreads();
        if (k0 + 8 < DD) {
            va = *(const float4*)(xrow + k0 + 8 + ka);
            vb = *(const float4*)(wrow + k0 + 8 + kb);
        }
#pragma unroll
        for (int kk = 0; kk < 8; kk++) {
            float4 a0 = *(const float4*)&As[kk][ty*8];
            float4 a1 = *(const float4*)&As[kk][ty*8 + 4];
            ull b[4];
#pragma unroll
            for (int jp = 0; jp < 4; jp++)
                b[jp] = *(const ull*)&Bs[kk][tx*8 + jp*2];
            float as[8] = {a0.x, a0.y, a0.z, a0.w, a1.x, a1.y, a1.z, a1.w};
#pragma unroll
            for (int i = 0; i < 8; i++) {
                ull a2 = pack2(as[i], as[i]);
#pragma unroll
                for (int jp = 0; jp < 4; jp++)
                    accp[i][jp] = fma2(a2, b[jp], accp[i][jp]);
            }
        }
        __syncthreads();
    }

    float biasv[8];
#pragma unroll
    for (int j = 0; j < 8; j++)
        biasv[j] = bt[(bn & 1023) + tx*8 + j];

#pragma unroll
    for (int i = 0; i < 8; i++) {
        size_t r = (size_t)(bm + ty*8 + i);
        float o[8];
#pragma unroll
        for (int jp = 0; jp < 4; jp++) unpack2(accp[i][jp], o[jp*2], o[jp*2+1]);
#pragma unroll
        for (int j = 0; j < 8; j++) o[j] += biasv[j];
        float4* dst = (float4*)&g_pre[r * N4H + bn + tx*8];
        dst[0] = make_float4(o[0], o[1], o[2], o[3]);
        dst[1] = make_float4(o[4], o[5], o[6], o[7]);
    }
}

// ============================================================================
// Step kernel v4b: tensor-core bf16 split-3 GEMM (hh*wh + hh*wl + hl*wh)
// 256 threads = 8 warps. C tile 128(b) x 32(n = 4 gates x 8 j).
// Warp tile m32 x n16. K chunks of 32, double-buffered, pitch-80B smem.
// B uses NON-trans ldmatrix ([n][k] smem layout matches the col-major B frag).
// ============================================================================
#define KC      32
#define APITCH  40                       // bf16 elems per row (80 B, conflict-free LDSM)
#define OFF_AHI 0                        // [2][128][APITCH]
#define OFF_ALO (2*128*APITCH)           // 10240
#define OFF_BHI (2*OFF_ALO)              // 20480  [2][32][APITCH]
#define OFF_BLO (OFF_BHI + 2*32*APITCH)  // 23040
#define SM_BF16 (OFF_BLO + 2*32*APITCH)  // 25600 bf16
#define STEP_SMEM_BYTES (SM_BF16 * 2)    // 51200 B

__global__ __launch_bounds__(256) void lstm_step_kernel(int t, float* __restrict__ out)
{
    extern __shared__ __nv_bfloat16 smb[];

    const int tid  = threadIdx.x;
    const int j0   = blockIdx.x * 8;
    const int wid  = tid >> 5, lane = tid & 31;
    const int wm   = wid >> 1;          // 0..3 : m-tile (rows wm*32..+31)
    const int wn   = wid & 1;           // 0..1 : n-tile (cols wn*16..+15)

    // ---- prefetch pre-activations + old cell state (hidden under GEMM) ----
    const float* preb = g_pre + (size_t)t * BB * N4H;
    float pr[4][4];
    float cold[4];
#pragma unroll
    for (int pp = 0; pp < 4; pp++) {
        int idx = tid + pp * 256;
        int b   = idx >> 3;
        int jl  = idx & 7;
#pragma unroll
        for (int g = 0; g < 4; g++)
            pr[pp][g] = preb[(size_t)b * N4H + g*1024 + j0 + jl];
        cold[pp] = (t > 0) ? g_c[b * HH + j0 + jl] : 0.0f;
    }

    float acc[2][2][4];
#pragma unroll
    for (int mt = 0; mt < 2; mt++)
#pragma unroll
        for (int nt = 0; nt < 2; nt++)
#pragma unroll
            for (int i = 0; i < 4; i++) acc[mt][nt][i] = 0.0f;

    if (t > 0) {
        // staging: A = h_hi/h_lo [128][KC], each thread 2 rows per array
        const int ar0 = tid >> 2;            // 0..63  (second row = +64)
        const int as0 = (tid & 3) * 8;       // 0,8,16,24 (bf16 elems)
        // B: 128 threads per array
        const int isLo = tid >> 7;
        const int bu = tid & 127;
        const int br = bu >> 2, bs = (bu & 3) * 8;
        const __nv_bfloat16* wsrc = isLo ? g_wlo : g_whi;
        const size_t wbase = (size_t)(blockIdx.x * 32 + br) * HH + bs;

        uint4 vh0, vh1, vl0, vl1, vw;
        vh0 = *(const uint4*)&g_hhi[(size_t)ar0 * HH + as0];
        vh1 = *(const uint4*)&g_hhi[(size_t)(ar0 + 64) * HH + as0];
        vl0 = *(const uint4*)&g_hlo[(size_t)ar0 * HH + as0];
        vl1 = *(const uint4*)&g_hlo[(size_t)(ar0 + 64) * HH + as0];
        vw  = *(const uint4*)&wsrc[wbase];

        // prime buffer 0
        *(uint4*)&smb[OFF_AHI + (0*128 + ar0)      * APITCH + as0] = vh0;
        *(uint4*)&smb[OFF_AHI + (0*128 + ar0 + 64) * APITCH + as0] = vh1;
        *(uint4*)&smb[OFF_ALO + (0*128 + ar0)      * APITCH + as0] = vl0;
        *(uint4*)&smb[OFF_ALO + (0*128 + ar0 + 64) * APITCH + as0] = vl1;
        *(uint4*)&smb[(isLo ? OFF_BLO : OFF_BHI) + (0*32 + br) * APITCH + bs] = vw;
        __syncthreads();

        // per-lane ldsm address components
        const int lrowA = (lane & 7) + ((lane >> 3) & 1) * 8;    // row-in-16
        const int lkA   = (lane >> 4) * 8;                        // +k8 for upper half
        const int gB    = lane >> 3;
        const int lrowB = wn * 16 + ((gB >> 1) & 1) * 8 + (lane & 7);
        const int lkB   = (gB & 1) * 8;

        int buf = 0;
        for (int k0 = 0; k0 < HH; k0 += KC) {
            if (k0 + KC < HH) {
                int kn = k0 + KC;
                vh0 = *(const uint4*)&g_hhi[(size_t)ar0 * HH + kn + as0];
                vh1 = *(const uint4*)&g_hhi[(size_t)(ar0 + 64) * HH + kn + as0];
                vl0 = *(const uint4*)&g_hlo[(size_t)ar0 * HH + kn + as0];
                vl1 = *(const uint4*)&g_hlo[(size_t)(ar0 + 64) * HH + kn + as0];
                vw  = *(const uint4*)&wsrc[wbase + kn];
            }
#pragma unroll
            for (int k16 = 0; k16 < 2; k16++) {
                uint ahi[2][4], alo[2][4], bhi[4], blo[4];
#pragma unroll
                for (int mt = 0; mt < 2; mt++) {
                    int r = wm * 32 + mt * 16 + lrowA;
                    int kk = k16 * 16 + lkA;
                    ldsm_x4(ahi[mt], sptr(&smb[OFF_AHI + (buf*128 + r) * APITCH + kk]));
                    ldsm_x4(alo[mt], sptr(&smb[OFF_ALO + (buf*128 + r) * APITCH + kk]));
                }
                {
                    int kk = k16 * 16 + lkB;
                    // NON-trans: smem [n][k] row-major == col-major B fragment
                    ldsm_x4(bhi, sptr(&smb[OFF_BHI + (buf*32 + lrowB) * APITCH + kk]));
                    ldsm_x4(blo, sptr(&smb[OFF_BLO + (buf*32 + lrowB) * APITCH + kk]));
                }
                // 3 split terms; interleave (mt,nt) so same-acc mmas are 4 apart
#pragma unroll
                for (int mt = 0; mt < 2; mt++)
#pragma unroll
                    for (int nt = 0; nt < 2; nt++)
                        mma16816(acc[mt][nt], ahi[mt], &bhi[nt*2]);
#pragma unroll
                for (int mt = 0; mt < 2; mt++)
#pragma unroll
                    for (int nt = 0; nt < 2; nt++)
                        mma16816(acc[mt][nt], ahi[mt], &blo[nt*2]);
#pragma unroll
                for (int mt = 0; mt < 2; mt++)
#pragma unroll
                    for (int nt = 0; nt < 2; nt++)
                        mma16816(acc[mt][nt], alo[mt], &bhi[nt*2]);
            }
            if (k0 + KC < HH) {
                int nb = buf ^ 1;
                *(uint4*)&smb[OFF_AHI + (nb*128 + ar0)      * APITCH + as0] = vh0;
                *(uint4*)&smb[OFF_AHI + (nb*128 + ar0 + 64) * APITCH + as0] = vh1;
                *(uint4*)&smb[OFF_ALO + (nb*128 + ar0)      * APITCH + as0] = vl0;
                *(uint4*)&smb[OFF_ALO + (nb*128 + ar0 + 64) * APITCH + as0] = vl1;
                *(uint4*)&smb[(isLo ? OFF_BLO : OFF_BHI) + (nb*32 + br) * APITCH + bs] = vw;
            }
            __syncthreads();
            buf ^= 1;
        }
    }

    // ---- write C frags to smem overlay (tiles dead after last sync) ----
    float* Gs = (float*)smb;    // [128][33]
#pragma unroll
    for (int mt = 0; mt < 2; mt++)
#pragma unroll
        for (int nt = 0; nt < 2; nt++) {
            int r = wm * 32 + mt * 16 + (lane >> 2);
            int c = wn * 16 + nt * 8 + (lane & 3) * 2;
            Gs[r * 33 + c]         = acc[mt][nt][0];
            Gs[r * 33 + c + 1]     = acc[mt][nt][1];
            Gs[(r + 8) * 33 + c]     = acc[mt][nt][2];
            Gs[(r + 8) * 33 + c + 1] = acc[mt][nt][3];
        }
    __syncthreads();

    // ---- fused cell update: 4 (b, jl) pairs per thread ----
#pragma unroll
    for (int pp = 0; pp < 4; pp++) {
        int idx = tid + pp * 256;
        int b   = idx >> 3;
        int jl  = idx & 7;
        float fg = sigmoidf_(Gs[b*33 + jl]       + pr[pp][0]);
        float ig = sigmoidf_(Gs[b*33 + 8  + jl]  + pr[pp][1]);
        float gv = tanhf   (Gs[b*33 + 16 + jl]   + pr[pp][2]);
        float og = sigmoidf_(Gs[b*33 + 24 + jl]  + pr[pp][3]);
        int cidx   = b * HH + j0 + jl;
        float cnew = fg * cold[pp] + ig * gv;
        float h    = og * tanhf(cnew);
        g_c[cidx] = cnew;
        __nv_bfloat16 hh = __float2bfloat16(h);
        g_hhi[cidx] = hh;
        g_hlo[cidx] = __float2bfloat16(h - __bfloat162float(hh));
        out[(size_t)t * BH + cidx] = h;
    }
}

__global__ void finalize_kernel(float* __restrict__ out, int write_state) {
    int i = blockIdx.x * blockDim.x + threadIdx.x;
    if (i < BH && write_state) {
        out[(size_t)TT * BH + i]       = out[(size_t)(TT - 1) * BH + i];  // hx
        out[(size_t)TT * BH + BH + i]  = g_c[i];                           // cx
    }
}

extern "C" void kernel_launch(void* const* d_in, const int* in_sizes, int n_in,
                              void* d_out, int out_size) {
    const float* X  = (const float*)d_in[0];
    const float* Wf = (const float*)d_in[1];
    const float* bf = (const float*)d_in[2];
    const float* Wi = (const float*)d_in[3];
    const float* bi = (const float*)d_in[4];
    const float* Wg = (const float*)d_in[5];
    const float* bg = (const float*)d_in[6];
    const float* Wo = (const float*)d_in[7];
    const float* bo = (const float*)d_in[8];
    float* out = (float*)d_out;

    cudaFuncSetAttribute(lstm_step_kernel,
                         cudaFuncAttributeMaxDynamicSharedMemorySize, STEP_SMEM_BYTES);

    // 0) split recurrent weights into bf16 hi/lo (block-ordered)
    split_w_kernel<<<(N4H * HH) / 256, 256>>>(Wf, Wi, Wg, Wo);

    // 1) time-parallel input projection (+bias)
    dim3 pgrid(N4H / 128, (TT * BB) / 128);
    pre_gemm_kernel<<<pgrid, 256>>>(X, Wf, Wi, Wg, Wo, bf, bi, bg, bo);

    // 2) sequential recurrence (tensor-core steps)
    for (int t = 0; t < TT; t++)
        lstm_step_kernel<<<HH / 8, 256, STEP_SMEM_BYTES>>>(t, out);

    // 3) final hx / cx
    int ws = (out_size >= TT * BH + 2 * BH) ? 1 : 0;
    finalize_kernel<<<(BH + 255) / 256, 256>>>(out, ws);
}

// round 11
// speedup vs baseline: 1.5162x; 1.0851x over previous
#include <cuda_runtime.h>
#include <cuda_bf16.h>
#include <math.h>

#define TT   256
#define BB   128
#define DD   1024
#define HH   1024
#define DH   2048
#define N4H  4096
#define BH   (BB*HH)
#define NBLK 128

typedef unsigned long long ull;
typedef unsigned int uint;

// Scratch (device globals — no allocation allowed)
__device__ float g_pre[(size_t)TT * BB * N4H];        // x-projection + bias, gate-major
__device__ float g_c[BH];                              // cell state [b, j]
__device__ __nv_bfloat16 g_hhi[2][BH];                 // h split-high, ping-pong [buf][b][k]
__device__ __nv_bfloat16 g_hlo[2][BH];                 // h split-low
__device__ __nv_bfloat16 g_whi[(size_t)N4H * HH];      // Wh split-high, block-ordered rows
__device__ __nv_bfloat16 g_wlo[(size_t)N4H * HH];      // Wh split-low

// grid barrier state (monotonic generation -> graph-replay safe)
__device__ int g_bar_cnt = 0;
__device__ volatile int g_bar_gen = 0;

// ---- packed fp32x2 helpers (pre-GEMM) ----
__device__ __forceinline__ ull pack2(float lo, float hi) {
    ull r; asm("mov.b64 %0, {%1, %2};" : "=l"(r) : "f"(lo), "f"(hi)); return r;
}
__device__ __forceinline__ void unpack2(ull v, float& lo, float& hi) {
    asm("mov.b64 {%0, %1}, %2;" : "=f"(lo), "=f"(hi) : "l"(v));
}
__device__ __forceinline__ ull fma2(ull a, ull b, ull c) {
    ull d; asm("fma.rn.f32x2 %0, %1, %2, %3;" : "=l"(d) : "l"(a), "l"(b), "l"(c)); return d;
}
__device__ __forceinline__ float sigmoidf_(float x) { return 1.0f / (1.0f + expf(-x)); }

// ---- mma helpers ----
__device__ __forceinline__ uint sptr(const void* p) { return (uint)__cvta_generic_to_shared(p); }
__device__ __forceinline__ void ldsm_x4(uint* r, uint addr) {
    asm volatile("ldmatrix.sync.aligned.m8n8.x4.shared.b16 {%0,%1,%2,%3}, [%4];"
        : "=r"(r[0]), "=r"(r[1]), "=r"(r[2]), "=r"(r[3]) : "r"(addr));
}
__device__ __forceinline__ void mma16816(float* c, const uint* a, const uint* b) {
    asm volatile("mma.sync.aligned.m16n8k16.row.col.f32.bf16.bf16.f32 "
        "{%0,%1,%2,%3}, {%4,%5,%6,%7}, {%8,%9}, {%0,%1,%2,%3};"
        : "+f"(c[0]), "+f"(c[1]), "+f"(c[2]), "+f"(c[3])
        : "r"(a[0]), "r"(a[1]), "r"(a[2]), "r"(a[3]), "r"(b[0]), "r"(b[1]));
}

// ============================================================================
// Weight split prep: Wh (recurrent region) -> bf16 hi/lo, block-ordered rows.
// ============================================================================
__global__ void split_w_kernel(
    const float* __restrict__ Wf, const float* __restrict__ Wi,
    const float* __restrict__ Wg, const float* __restrict__ Wo)
{
    int idx = blockIdx.x * 256 + threadIdx.x;
    int k = idx & 1023;
    int n = idx >> 10;
    int jblk = n >> 5, rem = n & 31, gate = rem >> 3, jl = rem & 7;
    const float* Wt = (gate == 0) ? Wf : (gate == 1) ? Wi : (gate == 2) ? Wg : Wo;
    float w = Wt[(size_t)(jblk * 8 + jl) * DH + DD + k];
    __nv_bfloat16 hi = __float2bfloat16(w);
    g_whi[idx] = hi;
    g_wlo[idx] = __float2bfloat16(w - __bfloat162float(hi));
}

// ============================================================================
// Pre-GEMM (fp32x2): g_pre = X @ Wx^T + bias   (unchanged)
// ============================================================================
__global__ __launch_bounds__(256, 2) void pre_gemm_kernel(
    const float* __restrict__ X,
    const float* __restrict__ Wf, const float* __restrict__ Wi,
    const float* __restrict__ Wg, const float* __restrict__ Wo,
    const float* __restrict__ bf, const float* __restrict__ bi,
    const float* __restrict__ bg, const float* __restrict__ bo)
{
    __shared__ float As[8][128];
    __shared__ float Bs[8][128];

    const int tid = threadIdx.x;
    const int bm  = blockIdx.y * 128;
    const int bn  = blockIdx.x * 128;
    const int gate = bn >> 10;

    const float* Wt = (gate == 0) ? Wf : (gate == 1) ? Wi : (gate == 2) ? Wg : Wo;
    const float* bt = (gate == 0) ? bf : (gate == 1) ? bi : (gate == 2) ? bg : bo;

    const int arow = tid >> 1;
    const int ka   = (tid & 1) * 4;
    const int ncol = tid >> 1;
    const int kb   = (tid & 1) * 4;
    const float* wrow = Wt + (size_t)((bn & 1023) + ncol) * DH;
    const float* xrow = X  + (size_t)(bm + arow) * DD;

    const int tx = tid & 15, ty = tid >> 4;

    ull accp[8][4];
#pragma unroll
    for (int i = 0; i < 8; i++)
#pragma unroll
        for (int jp = 0; jp < 4; jp++) accp[i][jp] = 0ULL;

    float4 va = *(const float4*)(xrow + ka);
    float4 vb = *(const float4*)(wrow + kb);

    for (int k0 = 0; k0 < DD; k0 += 8) {
        As[ka+0][arow] = va.x; As[ka+1][arow] = va.y; As[ka+2][arow] = va.z; As[ka+3][arow] = va.w;
        Bs[kb+0][ncol] = vb.x; Bs[kb+1][ncol] = vb.y; Bs[kb+2][ncol] = vb.z; Bs[kb+3][ncol] = vb.w;
        __syncthreads();
        if (k0 + 8 < DD) {
            va = *(const float4*)(xrow + k0 + 8 + ka);
            vb = *(const float4*)(wrow + k0 + 8 + kb);
        }
#pragma unroll
        for (int kk = 0; kk < 8; kk++) {
            float4 a0 = *(const float4*)&As[kk][ty*8];
            float4 a1 = *(const float4*)&As[kk][ty*8 + 4];
            ull b[4];
#pragma unroll
            for (int jp = 0; jp < 4; jp++)
                b[jp] = *(const ull*)&Bs[kk][tx*8 + jp*2];
            float as[8] = {a0.x, a0.y, a0.z, a0.w, a1.x, a1.y, a1.z, a1.w};
#pragma unroll
            for (int i = 0; i < 8; i++) {
                ull a2 = pack2(as[i], as[i]);
#pragma unroll
                for (int jp = 0; jp < 4; jp++)
                    accp[i][jp] = fma2(a2, b[jp], accp[i][jp]);
            }
        }
        __syncthreads();
    }

    float biasv[8];
#pragma unroll
    for (int j = 0; j < 8; j++)
        biasv[j] = bt[(bn & 1023) + tx*8 + j];

#pragma unroll
    for (int i = 0; i < 8; i++) {
        size_t r = (size_t)(bm + ty*8 + i);
        float o[8];
#pragma unroll
        for (int jp = 0; jp < 4; jp++) unpack2(accp[i][jp], o[jp*2], o[jp*2+1]);
#pragma unroll
        for (int j = 0; j < 8; j++) o[j] += biasv[j];
        float4* dst = (float4*)&g_pre[r * N4H + bn + tx*8];
        dst[0] = make_float4(o[0], o[1], o[2], o[3]);
        dst[1] = make_float4(o[4], o[5], o[6], o[7]);
    }
}

// ============================================================================
// Persistent recurrence kernel: 128 blocks (1/SM), weights resident in SMEM,
// h ping-pong in global, sense-reversing grid barrier between steps.
// Per step: bf16 split-3 GEMM (hh*wh + hh*wl + hl*wh) + fused cell update.
// ============================================================================
#define KC      32
#define APITCH  40                         // A chunk pitch (80 B, conflict-free)
#define WPITCH  1032                       // weight row pitch (2064 B -> 16B bank skew)
#define OFFW_HI 0                          // [32][WPITCH]
#define OFFW_LO (32*WPITCH)                // 33024
#define OFFA_HI (2*32*WPITCH)              // 66048  [2][128][APITCH]
#define OFFA_LO (OFFA_HI + 2*128*APITCH)   // 76288
#define SM_TOT  (OFFA_LO + 2*128*APITCH)   // 86528 bf16
#define PERSIST_SMEM_BYTES (SM_TOT * 2)    // 173056 B

__device__ __forceinline__ void grid_barrier() {
    __syncthreads();
    if (threadIdx.x == 0) {
        __threadfence();                       // publish this block's writes
        int gen = g_bar_gen;
        if (atomicAdd(&g_bar_cnt, 1) == NBLK - 1) {
            atomicExch(&g_bar_cnt, 0);
            __threadfence();
            g_bar_gen = gen + 1;               // release
        } else {
            while (g_bar_gen == gen) __nanosleep(40);
            __threadfence();                   // acquire
        }
    }
    __syncthreads();
}

__global__ __launch_bounds__(256) void lstm_persist_kernel(float* __restrict__ out,
                                                           int write_state)
{
    extern __shared__ __nv_bfloat16 smb[];

    const int tid  = threadIdx.x;
    const int blk  = blockIdx.x;
    const int j0   = blk * 8;
    const int wid  = tid >> 5, lane = tid & 31;
    const int wm   = wid >> 1;          // 0..3 : m-tile (rows wm*32..+31)
    const int wn   = wid & 1;           // 0..1 : n-tile (cols wn*16..+15)

    // ---- load this block's weights into smem ONCE (hi+lo, 132 KB) ----
    for (int i = tid; i < 32 * 128; i += 256) {          // 4096 uint4 per array
        int r = i >> 7, c8 = (i & 127) * 8;
        *(uint4*)&smb[OFFW_HI + r*WPITCH + c8] = *(const uint4*)&g_whi[((size_t)blk*32 + r)*HH + c8];
        *(uint4*)&smb[OFFW_LO + r*WPITCH + c8] = *(const uint4*)&g_wlo[((size_t)blk*32 + r)*HH + c8];
    }
    __syncthreads();

    // per-lane ldsm address components (proven in round-10 kernel)
    const int lrowA = (lane & 7) + ((lane >> 3) & 1) * 8;
    const int lkA   = (lane >> 4) * 8;
    const int gB    = lane >> 3;
    const int lrowB = wn * 16 + ((gB >> 1) & 1) * 8 + (lane & 7);
    const int lkB   = (gB & 1) * 8;

    // A staging geometry
    const int ar0 = tid >> 2;            // 0..63 (second row = +64)
    const int as0 = (tid & 3) * 8;       // bf16 offset within row

    for (int t = 0; t < TT; t++) {
        // ---- prefetch pre-activations + old cell state (consumed in epilogue) ----
        const float* preb = g_pre + (size_t)t * BB * N4H;
        float pr[4][4];
        float cold[4];
#pragma unroll
        for (int pp = 0; pp < 4; pp++) {
            int idx = tid + pp * 256;
            int b   = idx >> 3;
            int jl  = idx & 7;
#pragma unroll
            for (int g = 0; g < 4; g++)
                pr[pp][g] = preb[(size_t)b * N4H + g*1024 + j0 + jl];
            cold[pp] = (t > 0) ? g_c[b * HH + j0 + jl] : 0.0f;
        }

        float acc[2][2][4];
#pragma unroll
        for (int mt = 0; mt < 2; mt++)
#pragma unroll
            for (int nt = 0; nt < 2; nt++)
#pragma unroll
                for (int i = 0; i < 4; i++) acc[mt][nt][i] = 0.0f;

        if (t > 0) {
            const __nv_bfloat16* hsrc_hi = g_hhi[t & 1];
            const __nv_bfloat16* hsrc_lo = g_hlo[t & 1];

            uint4 vh0, vh1, vl0, vl1;
            vh0 = *(const uint4*)&hsrc_hi[(size_t)ar0 * HH + as0];
            vh1 = *(const uint4*)&hsrc_hi[(size_t)(ar0 + 64) * HH + as0];
            vl0 = *(const uint4*)&hsrc_lo[(size_t)ar0 * HH + as0];
            vl1 = *(const uint4*)&hsrc_lo[(size_t)(ar0 + 64) * HH + as0];

            // prime buffer 0
            *(uint4*)&smb[OFFA_HI + (0*128 + ar0)      * APITCH + as0] = vh0;
            *(uint4*)&smb[OFFA_HI + (0*128 + ar0 + 64) * APITCH + as0] = vh1;
            *(uint4*)&smb[OFFA_LO + (0*128 + ar0)      * APITCH + as0] = vl0;
            *(uint4*)&smb[OFFA_LO + (0*128 + ar0 + 64) * APITCH + as0] = vl1;
            __syncthreads();

            int buf = 0;
            for (int k0 = 0; k0 < HH; k0 += KC) {
                if (k0 + KC < HH) {
                    int kn = k0 + KC;
                    vh0 = *(const uint4*)&hsrc_hi[(size_t)ar0 * HH + kn + as0];
                    vh1 = *(const uint4*)&hsrc_hi[(size_t)(ar0 + 64) * HH + kn + as0];
                    vl0 = *(const uint4*)&hsrc_lo[(size_t)ar0 * HH + kn + as0];
                    vl1 = *(const uint4*)&hsrc_lo[(size_t)(ar0 + 64) * HH + kn + as0];
                }
#pragma unroll
                for (int k16 = 0; k16 < 2; k16++) {
                    uint ahi[2][4], alo[2][4], bhi[4], blo[4];
#pragma unroll
                    for (int mt = 0; mt < 2; mt++) {
                        int r = wm * 32 + mt * 16 + lrowA;
                        int kk = k16 * 16 + lkA;
                        ldsm_x4(ahi[mt], sptr(&smb[OFFA_HI + (buf*128 + r) * APITCH + kk]));
                        ldsm_x4(alo[mt], sptr(&smb[OFFA_LO + (buf*128 + r) * APITCH + kk]));
                    }
                    {
                        int kk = k0 + k16 * 16 + lkB;   // B straight from resident weights
                        ldsm_x4(bhi, sptr(&smb[OFFW_HI + lrowB * WPITCH + kk]));
                        ldsm_x4(blo, sptr(&smb[OFFW_LO + lrowB * WPITCH + kk]));
                    }
#pragma unroll
                    for (int mt = 0; mt < 2; mt++)
#pragma unroll
                        for (int nt = 0; nt < 2; nt++)
                            mma16816(acc[mt][nt], ahi[mt], &bhi[nt*2]);
#pragma unroll
                    for (int mt = 0; mt < 2; mt++)
#pragma unroll
                        for (int nt = 0; nt < 2; nt++)
                            mma16816(acc[mt][nt], ahi[mt], &blo[nt*2]);
#pragma unroll
                    for (int mt = 0; mt < 2; mt++)
#pragma unroll
                        for (int nt = 0; nt < 2; nt++)
                            mma16816(acc[mt][nt], alo[mt], &bhi[nt*2]);
                }
                if (k0 + KC < HH) {
                    int nb = buf ^ 1;
                    *(uint4*)&smb[OFFA_HI + (nb*128 + ar0)      * APITCH + as0] = vh0;
                    *(uint4*)&smb[OFFA_HI + (nb*128 + ar0 + 64) * APITCH + as0] = vh1;
                    *(uint4*)&smb[OFFA_LO + (nb*128 + ar0)      * APITCH + as0] = vl0;
                    *(uint4*)&smb[OFFA_LO + (nb*128 + ar0 + 64) * APITCH + as0] = vl1;
                }
                __syncthreads();
                buf ^= 1;
            }
        }

        // ---- write C frags to smem overlay (A region is dead now) ----
        float* Gs = (float*)&smb[OFFA_HI];    // [128][33] floats = 16.9 KB <= 40.9 KB
#pragma unroll
        for (int mt = 0; mt < 2; mt++)
#pragma unroll
            for (int nt = 0; nt < 2; nt++) {
                int r = wm * 32 + mt * 16 + (lane >> 2);
                int c = wn * 16 + nt * 8 + (lane & 3) * 2;
                Gs[r * 33 + c]           = acc[mt][nt][0];
                Gs[r * 33 + c + 1]       = acc[mt][nt][1];
                Gs[(r + 8) * 33 + c]     = acc[mt][nt][2];
                Gs[(r + 8) * 33 + c + 1] = acc[mt][nt][3];
            }
        __syncthreads();

        // ---- fused cell update: 4 (b, jl) pairs per thread ----
        __nv_bfloat16* hdst_hi = g_hhi[(t + 1) & 1];
        __nv_bfloat16* hdst_lo = g_hlo[(t + 1) & 1];
#pragma unroll
        for (int pp = 0; pp < 4; pp++) {
            int idx = tid + pp * 256;
            int b   = idx >> 3;
            int jl  = idx & 7;
            float fg = sigmoidf_(Gs[b*33 + jl]       + pr[pp][0]);
            float ig = sigmoidf_(Gs[b*33 + 8  + jl]  + pr[pp][1]);
            float gv = tanhf   (Gs[b*33 + 16 + jl]   + pr[pp][2]);
            float og = sigmoidf_(Gs[b*33 + 24 + jl]  + pr[pp][3]);
            int cidx   = b * HH + j0 + jl;
            float cnew = fg * cold[pp] + ig * gv;
            float h    = og * tanhf(cnew);
            g_c[cidx] = cnew;
            __nv_bfloat16 hh = __float2bfloat16(h);
            hdst_hi[cidx] = hh;
            hdst_lo[cidx] = __float2bfloat16(h - __bfloat162float(hh));
            out[(size_t)t * BH + cidx] = h;
            if (t == TT - 1 && write_state) {
                out[(size_t)TT * BH + cidx]      = h;       // hx
                out[(size_t)TT * BH + BH + cidx] = cnew;    // cx
            }
        }

        if (t < TT - 1) grid_barrier();    // publish h for step t+1
    }
}

extern "C" void kernel_launch(void* const* d_in, const int* in_sizes, int n_in,
                              void* d_out, int out_size) {
    const float* X  = (const float*)d_in[0];
    const float* Wf = (const float*)d_in[1];
    const float* bf = (const float*)d_in[2];
    const float* Wi = (const float*)d_in[3];
    const float* bi = (const float*)d_in[4];
    const float* Wg = (const float*)d_in[5];
    const float* bg = (const float*)d_in[6];
    const float* Wo = (const float*)d_in[7];
    const float* bo = (const float*)d_in[8];
    float* out = (float*)d_out;

    cudaFuncSetAttribute(lstm_persist_kernel,
                         cudaFuncAttributeMaxDynamicSharedMemorySize, PERSIST_SMEM_BYTES);

    // 0) split recurrent weights into bf16 hi/lo (block-ordered)
    split_w_kernel<<<(N4H * HH) / 256, 256>>>(Wf, Wi, Wg, Wo);

    // 1) time-parallel input projection (+bias)
    dim3 pgrid(N4H / 128, (TT * BB) / 128);
    pre_gemm_kernel<<<pgrid, 256>>>(X, Wf, Wi, Wg, Wo, bf, bi, bg, bo);

    // 2) whole recurrence in ONE persistent kernel (weights SMEM-resident)
    int ws = (out_size >= TT * BH + 2 * BH) ? 1 : 0;
    lstm_persist_kernel<<<NBLK, 256, PERSIST_SMEM_BYTES>>>(out, ws);
}

// round 12
// speedup vs baseline: 2.2904x; 1.5106x over previous
#include <cuda_runtime.h>
#include <cuda_bf16.h>
#include <math.h>

#define TT   256
#define BB   128
#define DD   1024
#define HH   1024
#define DH   2048
#define N4H  4096
#define BH   (BB*HH)
#define NBLK 128

typedef unsigned long long ull;
typedef unsigned int uint;

// Scratch (device globals — no allocation allowed)
__device__ float g_pre[(size_t)TT * BB * N4H];        // x-projection + bias, gate-major cols
__device__ float g_c[BH];                              // cell state [b, j]
__device__ __nv_bfloat16 g_hhi[2][BH];                 // h split-high, ping-pong [buf][b][k]
__device__ __nv_bfloat16 g_hlo[2][BH];                 // h split-low
__device__ __nv_bfloat16 g_whi[(size_t)N4H * HH];      // Wh split-high, block-ordered rows
__device__ __nv_bfloat16 g_wlo[(size_t)N4H * HH];      // Wh split-low
__device__ __nv_bfloat16 g_xhi[(size_t)TT * BB * DD];  // X split-high [T*B][D]
__device__ __nv_bfloat16 g_xlo[(size_t)TT * BB * DD];  // X split-low
__device__ __nv_bfloat16 g_wxhi[(size_t)N4H * DD];     // Wx split-high, rows n = gate*1024+j
__device__ __nv_bfloat16 g_wxlo[(size_t)N4H * DD];     // Wx split-low

// grid barrier state
__device__ int g_bar_cnt = 0;
__device__ volatile int g_bar_gen = 0;

__device__ __forceinline__ float sigmoidf_(float x) { return 1.0f / (1.0f + expf(-x)); }

// ---- mma / async helpers ----
__device__ __forceinline__ uint sptr(const void* p) { return (uint)__cvta_generic_to_shared(p); }
__device__ __forceinline__ void ldsm_x4(uint* r, uint addr) {
    asm volatile("ldmatrix.sync.aligned.m8n8.x4.shared.b16 {%0,%1,%2,%3}, [%4];"
        : "=r"(r[0]), "=r"(r[1]), "=r"(r[2]), "=r"(r[3]) : "r"(addr));
}
__device__ __forceinline__ void mma16816(float* c, const uint* a, const uint* b) {
    asm volatile("mma.sync.aligned.m16n8k16.row.col.f32.bf16.bf16.f32 "
        "{%0,%1,%2,%3}, {%4,%5,%6,%7}, {%8,%9}, {%0,%1,%2,%3};"
        : "+f"(c[0]), "+f"(c[1]), "+f"(c[2]), "+f"(c[3])
        : "r"(a[0]), "r"(a[1]), "r"(a[2]), "r"(a[3]), "r"(b[0]), "r"(b[1]));
}
__device__ __forceinline__ void cp16(uint dst, const void* src) {
    asm volatile("cp.async.cg.shared.global [%0], [%1], 16;" :: "r"(dst), "l"(src));
}
#define CP_COMMIT() asm volatile("cp.async.commit_group;" ::: "memory")
#define CP_WAIT(n)  asm volatile("cp.async.wait_group %0;" :: "n"(n) : "memory")

// ============================================================================
// Split kernels: fp32 -> bf16 hi/lo
// ============================================================================
__global__ void split_wh_kernel(
    const float* __restrict__ Wf, const float* __restrict__ Wi,
    const float* __restrict__ Wg, const float* __restrict__ Wo)
{
    int idx = blockIdx.x * 256 + threadIdx.x;
    int k = idx & 1023;
    int n = idx >> 10;
    int jblk = n >> 5, rem = n & 31, gate = rem >> 3, jl = rem & 7;
    const float* Wt = (gate == 0) ? Wf : (gate == 1) ? Wi : (gate == 2) ? Wg : Wo;
    float w = Wt[(size_t)(jblk * 8 + jl) * DH + DD + k];
    __nv_bfloat16 hi = __float2bfloat16(w);
    g_whi[idx] = hi;
    g_wlo[idx] = __float2bfloat16(w - __bfloat162float(hi));
}

__global__ void split_wx_kernel(
    const float* __restrict__ Wf, const float* __restrict__ Wi,
    const float* __restrict__ Wg, const float* __restrict__ Wo)
{
    int idx = blockIdx.x * 256 + threadIdx.x;      // 0 .. 4096*1024-1
    int k = idx & 1023;
    int n = idx >> 10;                             // n = gate*1024 + j (g_pre col order)
    int gate = n >> 10, j = n & 1023;
    const float* Wt = (gate == 0) ? Wf : (gate == 1) ? Wi : (gate == 2) ? Wg : Wo;
    float w = Wt[(size_t)j * DH + k];              // x-part cols [0, D)
    __nv_bfloat16 hi = __float2bfloat16(w);
    g_wxhi[idx] = hi;
    g_wxlo[idx] = __float2bfloat16(w - __bfloat162float(hi));
}

__global__ void split_x_kernel(const float* __restrict__ X) {
    size_t idx = (size_t)blockIdx.x * 256 + threadIdx.x;   // 0 .. T*B*D-1
    float v = X[idx];
    __nv_bfloat16 hi = __float2bfloat16(v);
    g_xhi[idx] = hi;
    g_xlo[idx] = __float2bfloat16(v - __bfloat162float(hi));
}

// ============================================================================
// Pre-GEMM (tensor core, split-3): g_pre[32768, 4096] = X @ Wx^T + bias
// Grid (32 n-tiles fastest, 256 m-tiles). Block 256 thr = 8 warps (4m x 2n),
// warp tile m32 x n64. K chunks 32, 3-stage cp.async pipeline. Pitch-80B smem.
// ============================================================================
#define PKC     32
#define PPITCH  40
#define PSTG    (128*PPITCH)             // 5120 bf16 per stage slab
#define PA_HI   0                        // [3][128][40]
#define PA_LO   (3*PSTG)                 // 15360
#define PB_HI   (6*PSTG)                 // 30720
#define PB_LO   (9*PSTG)                 // 46080
#define PBIAS   (12*PSTG)                // 61440 (128 floats)
#define PRE_SMEM_BYTES (PBIAS*2 + 128*4) // 123392 B

__global__ __launch_bounds__(256) void pre_gemm_bf16_kernel(
    const float* __restrict__ bf, const float* __restrict__ bi,
    const float* __restrict__ bg, const float* __restrict__ bo)
{
    extern __shared__ __nv_bfloat16 smb[];
    const int tid  = threadIdx.x;
    const int nb   = blockIdx.x;            // 0..31
    const int mb   = blockIdx.y;            // 0..255
    const int wid  = tid >> 5, lane = tid & 31;
    const int wm   = wid & 3;               // m-tile rows wm*32..+31
    const int wn   = wid >> 2;              // n-tile cols wn*64..+63

    // bias -> smem
    float* biasS = (float*)&smb[PBIAS];
    if (tid < 128) {
        int gate = nb >> 3;
        const float* bt = (gate == 0) ? bf : (gate == 1) ? bi : (gate == 2) ? bg : bo;
        biasS[tid] = bt[(nb & 7) * 128 + tid];
    }

    // staging geometry: 2 threads per row, 16 bf16 each (2 x 16B)
    const int ar  = tid >> 1;               // 0..127
    const int ks0 = (tid & 1) * 16;         // bf16 offset in chunk
    const size_t asrc = (size_t)(mb * 128 + ar) * DD + ks0;
    const size_t bsrc = (size_t)(nb * 128 + ar) * DD + ks0;

#define PRE_ISSUE(c, s) do {                                                      \
    size_t ko = (size_t)(c) * PKC;                                                \
    uint da = sptr(&smb[PA_HI + (s)*PSTG + ar*PPITCH + ks0]);                     \
    uint db = sptr(&smb[PB_HI + (s)*PSTG + ar*PPITCH + ks0]);                     \
    cp16(da,                         &g_xhi[asrc + ko]);                          \
    cp16(da + 16,                    &g_xhi[asrc + ko + 8]);                      \
    cp16(da + (PA_LO-PA_HI)*2,       &g_xlo[asrc + ko]);                          \
    cp16(da + (PA_LO-PA_HI)*2 + 16,  &g_xlo[asrc + ko + 8]);                      \
    cp16(db,                         &g_wxhi[bsrc + ko]);                         \
    cp16(db + 16,                    &g_wxhi[bsrc + ko + 8]);                     \
    cp16(db + (PB_LO-PB_HI)*2,       &g_wxlo[bsrc + ko]);                         \
    cp16(db + (PB_LO-PB_HI)*2 + 16,  &g_wxlo[bsrc + ko + 8]);                     \
} while (0)

    float acc[2][8][4];
#pragma unroll
    for (int mt = 0; mt < 2; mt++)
#pragma unroll
        for (int n8 = 0; n8 < 8; n8++)
#pragma unroll
            for (int i = 0; i < 4; i++) acc[mt][n8][i] = 0.0f;

    // ldsm lane components (proven mapping)
    const int lrowA = (lane & 7) + ((lane >> 3) & 1) * 8;
    const int lkA   = (lane >> 4) * 8;
    const int gB    = lane >> 3;
    const int lrowB = ((gB >> 1) & 1) * 8 + (lane & 7);
    const int lkB   = (gB & 1) * 8;

    // prologue: 2 chunks ahead
    PRE_ISSUE(0, 0); CP_COMMIT();
    PRE_ISSUE(1, 1); CP_COMMIT();

    for (int c = 0; c < DD / PKC; c++) {
        CP_WAIT(1);
        __syncthreads();
        const int stg = c % 3;
#pragma unroll
        for (int k16 = 0; k16 < 2; k16++) {
            uint ahi[2][4], alo[2][4], bh[4][4], bl[4][4];
#pragma unroll
            for (int mt = 0; mt < 2; mt++) {
                int r = wm * 32 + mt * 16 + lrowA;
                int kk = k16 * 16 + lkA;
                ldsm_x4(ahi[mt], sptr(&smb[PA_HI + stg*PSTG + r*PPITCH + kk]));
                ldsm_x4(alo[mt], sptr(&smb[PA_LO + stg*PSTG + r*PPITCH + kk]));
            }
#pragma unroll
            for (int g = 0; g < 4; g++) {
                int r = wn * 64 + g * 16 + lrowB;
                int kk = k16 * 16 + lkB;
                ldsm_x4(bh[g], sptr(&smb[PB_HI + stg*PSTG + r*PPITCH + kk]));
                ldsm_x4(bl[g], sptr(&smb[PB_LO + stg*PSTG + r*PPITCH + kk]));
            }
#pragma unroll
            for (int g = 0; g < 4; g++)
#pragma unroll
                for (int mt = 0; mt < 2; mt++)
#pragma unroll
                    for (int nt = 0; nt < 2; nt++)
                        mma16816(acc[mt][g*2+nt], ahi[mt], &bh[g][nt*2]);
#pragma unroll
            for (int g = 0; g < 4; g++)
#pragma unroll
                for (int mt = 0; mt < 2; mt++)
#pragma unroll
                    for (int nt = 0; nt < 2; nt++)
                        mma16816(acc[mt][g*2+nt], ahi[mt], &bl[g][nt*2]);
#pragma unroll
            for (int g = 0; g < 4; g++)
#pragma unroll
                for (int mt = 0; mt < 2; mt++)
#pragma unroll
                    for (int nt = 0; nt < 2; nt++)
                        mma16816(acc[mt][g*2+nt], alo[mt], &bh[g][nt*2]);
        }
        if (c + 2 < DD / PKC) PRE_ISSUE(c + 2, (c + 2) % 3);
        CP_COMMIT();
    }

    // epilogue: bias add + store (frag mapping proven in step kernel)
#pragma unroll
    for (int mt = 0; mt < 2; mt++)
#pragma unroll
        for (int g = 0; g < 4; g++)
#pragma unroll
            for (int nt = 0; nt < 2; nt++) {
                int r  = wm * 32 + mt * 16 + (lane >> 2);
                int cl = wn * 64 + g * 16 + nt * 8 + (lane & 3) * 2;
                float b0 = biasS[cl], b1 = biasS[cl + 1];
                float* d0 = &g_pre[(size_t)(mb * 128 + r) * N4H + nb * 128 + cl];
                float* d1 = &g_pre[(size_t)(mb * 128 + r + 8) * N4H + nb * 128 + cl];
                d0[0] = acc[mt][g*2+nt][0] + b0;
                d0[1] = acc[mt][g*2+nt][1] + b1;
                d1[0] = acc[mt][g*2+nt][2] + b0;
                d1[1] = acc[mt][g*2+nt][3] + b1;
            }
#undef PRE_ISSUE
}

// ============================================================================
// Persistent recurrence kernel: 128 blocks (1/SM), weights SMEM-resident,
// h via 4-stage cp.async pipeline, grid barrier between steps.
// ============================================================================
#define KC      32
#define APITCH  40
#define WPITCH  1032
#define OFFW_HI 0                          // [32][1032]
#define OFFW_LO (32*WPITCH)                // 33024
#define OFFA_HI (2*32*WPITCH)              // 66048  [4][128][40]
#define OFFA_LO (OFFA_HI + 4*128*APITCH)   // 86528
#define SM_TOT  (OFFA_LO + 4*128*APITCH)   // 107008 bf16
#define PERSIST_SMEM_BYTES (SM_TOT * 2)    // 214016 B

__device__ __forceinline__ void grid_barrier() {
    __syncthreads();
    if (threadIdx.x == 0) {
        __threadfence();
        int gen = g_bar_gen;
        if (atomicAdd(&g_bar_cnt, 1) == NBLK - 1) {
            atomicExch(&g_bar_cnt, 0);
            __threadfence();
            g_bar_gen = gen + 1;
        } else {
            while (g_bar_gen == gen) __nanosleep(40);
            __threadfence();
        }
    }
    __syncthreads();
}

__global__ __launch_bounds__(256) void lstm_persist_kernel(float* __restrict__ out,
                                                           int write_state)
{
    extern __shared__ __nv_bfloat16 smb[];

    const int tid  = threadIdx.x;
    const int blk  = blockIdx.x;
    const int j0   = blk * 8;
    const int wid  = tid >> 5, lane = tid & 31;
    const int wm   = wid >> 1;
    const int wn   = wid & 1;

    // weights -> smem once
    for (int i = tid; i < 32 * 128; i += 256) {
        int r = i >> 7, c8 = (i & 127) * 8;
        *(uint4*)&smb[OFFW_HI + r*WPITCH + c8] = *(const uint4*)&g_whi[((size_t)blk*32 + r)*HH + c8];
        *(uint4*)&smb[OFFW_LO + r*WPITCH + c8] = *(const uint4*)&g_wlo[((size_t)blk*32 + r)*HH + c8];
    }
    __syncthreads();

    const int lrowA = (lane & 7) + ((lane >> 3) & 1) * 8;
    const int lkA   = (lane >> 4) * 8;
    const int gB    = lane >> 3;
    const int lrowB = wn * 16 + ((gB >> 1) & 1) * 8 + (lane & 7);
    const int lkB   = (gB & 1) * 8;

    // A staging: 4 threads/row, 8 bf16 (16B) each; rows ar0 and ar0+64
    const int ar0 = tid >> 2;
    const int as0 = (tid & 3) * 8;

    for (int t = 0; t < TT; t++) {
        const float* preb = g_pre + (size_t)t * BB * N4H;
        float pr[4][4];
        float cold[4];
#pragma unroll
        for (int pp = 0; pp < 4; pp++) {
            int idx = tid + pp * 256;
            int b   = idx >> 3;
            int jl  = idx & 7;
#pragma unroll
            for (int g = 0; g < 4; g++)
                pr[pp][g] = preb[(size_t)b * N4H + g*1024 + j0 + jl];
            cold[pp] = (t > 0) ? g_c[b * HH + j0 + jl] : 0.0f;
        }

        float acc[2][2][4];
#pragma unroll
        for (int mt = 0; mt < 2; mt++)
#pragma unroll
            for (int nt = 0; nt < 2; nt++)
#pragma unroll
                for (int i = 0; i < 4; i++) acc[mt][nt][i] = 0.0f;

        if (t > 0) {
            const __nv_bfloat16* hsrc_hi = g_hhi[t & 1];
            const __nv_bfloat16* hsrc_lo = g_hlo[t & 1];

#define PST_ISSUE(c, s) do {                                                        \
    int ko = (c) * KC + as0;                                                        \
    uint d0 = sptr(&smb[OFFA_HI + ((s)*128 + ar0)      * APITCH + as0]);            \
    uint d1 = sptr(&smb[OFFA_HI + ((s)*128 + ar0 + 64) * APITCH + as0]);            \
    cp16(d0,                        &hsrc_hi[(size_t)ar0        * HH + ko]);        \
    cp16(d1,                        &hsrc_hi[(size_t)(ar0 + 64) * HH + ko]);        \
    cp16(d0 + (OFFA_LO-OFFA_HI)*2,  &hsrc_lo[(size_t)ar0        * HH + ko]);        \
    cp16(d1 + (OFFA_LO-OFFA_HI)*2,  &hsrc_lo[(size_t)(ar0 + 64) * HH + ko]);        \
} while (0)

            PST_ISSUE(0, 0); CP_COMMIT();
            PST_ISSUE(1, 1); CP_COMMIT();
            PST_ISSUE(2, 2); CP_COMMIT();

            for (int kc = 0; kc < HH / KC; kc++) {
                CP_WAIT(2);
                __syncthreads();
                const int stg = kc & 3;
#pragma unroll
                for (int k16 = 0; k16 < 2; k16++) {
                    uint ahi[2][4], alo[2][4], bhi[4], blo[4];
#pragma unroll
                    for (int mt = 0; mt < 2; mt++) {
                        int r = wm * 32 + mt * 16 + lrowA;
                        int kk = k16 * 16 + lkA;
                        ldsm_x4(ahi[mt], sptr(&smb[OFFA_HI + (stg*128 + r) * APITCH + kk]));
                        ldsm_x4(alo[mt], sptr(&smb[OFFA_LO + (stg*128 + r) * APITCH + kk]));
                    }
                    {
                        int kk = kc * KC + k16 * 16 + lkB;
                        ldsm_x4(bhi, sptr(&smb[OFFW_HI + lrowB * WPITCH + kk]));
                        ldsm_x4(blo, sptr(&smb[OFFW_LO + lrowB * WPITCH + kk]));
                    }
#pragma unroll
                    for (int mt = 0; mt < 2; mt++)
#pragma unroll
                        for (int nt = 0; nt < 2; nt++)
                            mma16816(acc[mt][nt], ahi[mt], &bhi[nt*2]);
#pragma unroll
                    for (int mt = 0; mt < 2; mt++)
#pragma unroll
                        for (int nt = 0; nt < 2; nt++)
                            mma16816(acc[mt][nt], ahi[mt], &blo[nt*2]);
#pragma unroll
                    for (int mt = 0; mt < 2; mt++)
#pragma unroll
                        for (int nt = 0; nt < 2; nt++)
                            mma16816(acc[mt][nt], alo[mt], &bhi[nt*2]);
                }
                int nc = kc + 3;
                if (nc < HH / KC) PST_ISSUE(nc, nc & 3);
                CP_COMMIT();
            }
#undef PST_ISSUE
        }

        // write C frags to smem overlay (stage-0 A region is dead)
        float* Gs = (float*)&smb[OFFA_HI];    // [128][33] = 16.9 KB
        __syncthreads();
#pragma unroll
        for (int mt = 0; mt < 2; mt++)
#pragma unroll
            for (int nt = 0; nt < 2; nt++) {
                int r = wm * 32 + mt * 16 + (lane >> 2);
                int c = wn * 16 + nt * 8 + (lane & 3) * 2;
                Gs[r * 33 + c]           = acc[mt][nt][0];
                Gs[r * 33 + c + 1]       = acc[mt][nt][1];
                Gs[(r + 8) * 33 + c]     = acc[mt][nt][2];
                Gs[(r + 8) * 33 + c + 1] = acc[mt][nt][3];
            }
        __syncthreads();

        // fused cell update
        __nv_bfloat16* hdst_hi = g_hhi[(t + 1) & 1];
        __nv_bfloat16* hdst_lo = g_hlo[(t + 1) & 1];
#pragma unroll
        for (int pp = 0; pp < 4; pp++) {
            int idx = tid + pp * 256;
            int b   = idx >> 3;
            int jl  = idx & 7;
            float fg = sigmoidf_(Gs[b*33 + jl]       + pr[pp][0]);
            float ig = sigmoidf_(Gs[b*33 + 8  + jl]  + pr[pp][1]);
            float gv = tanhf   (Gs[b*33 + 16 + jl]   + pr[pp][2]);
            float og = sigmoidf_(Gs[b*33 + 24 + jl]  + pr[pp][3]);
            int cidx   = b * HH + j0 + jl;
            float cnew = fg * cold[pp] + ig * gv;
            float h    = og * tanhf(cnew);
            g_c[cidx] = cnew;
            __nv_bfloat16 hh = __float2bfloat16(h);
            hdst_hi[cidx] = hh;
            hdst_lo[cidx] = __float2bfloat16(h - __bfloat162float(hh));
            out[(size_t)t * BH + cidx] = h;
            if (t == TT - 1 && write_state) {
                out[(size_t)TT * BH + cidx]      = h;       // hx
                out[(size_t)TT * BH + BH + cidx] = cnew;    // cx
            }
        }

        if (t < TT - 1) grid_barrier();
    }
}

extern "C" void kernel_launch(void* const* d_in, const int* in_sizes, int n_in,
                              void* d_out, int out_size) {
    const float* X  = (const float*)d_in[0];
    const float* Wf = (const float*)d_in[1];
    const float* bf = (const float*)d_in[2];
    const float* Wi = (const float*)d_in[3];
    const float* bi = (const float*)d_in[4];
    const float* Wg = (const float*)d_in[5];
    const float* bg = (const float*)d_in[6];
    const float* Wo = (const float*)d_in[7];
    const float* bo = (const float*)d_in[8];
    float* out = (float*)d_out;

    cudaFuncSetAttribute(lstm_persist_kernel,
                         cudaFuncAttributeMaxDynamicSharedMemorySize, PERSIST_SMEM_BYTES);
    cudaFuncSetAttribute(pre_gemm_bf16_kernel,
                         cudaFuncAttributeMaxDynamicSharedMemorySize, PRE_SMEM_BYTES);

    // 0) fp32 -> bf16 hi/lo splits
    split_wh_kernel<<<(N4H * HH) / 256, 256>>>(Wf, Wi, Wg, Wo);
    split_wx_kernel<<<(N4H * DD) / 256, 256>>>(Wf, Wi, Wg, Wo);
    split_x_kernel<<<(TT * BB * DD) / 256, 256>>>(X);

    // 1) time-parallel input projection (+bias), tensor-core split-3
    dim3 pgrid(N4H / 128, (TT * BB) / 128);   // x = n (fastest) -> X panel L2 reuse
    pre_gemm_bf16_kernel<<<pgrid, 256, PRE_SMEM_BYTES>>>(bf, bi, bg, bo);

    // 2) whole recurrence in ONE persistent kernel
    int ws = (out_size >= TT * BH + 2 * BH) ? 1 : 0;
    lstm_persist_kernel<<<NBLK, 256, PERSIST_SMEM_BYTES>>>(out, ws);
}